// round 14
// baseline (speedup 1.0000x reference)
#include <cuda_runtime.h>

// Problem constants
#define NUM_U    4
#define NUM_NT   8
#define NPER     (128 * 49152)        // elements per user = 6,291,456
#define N8       (NPER / 8)           // float8 positions per user = 786,432
#define THREADS  256
#define IPT8     2                    // float8 positions per thread
#define GRID     (N8 / (THREADS * IPT8))  // 1536 blocks, exact cover

// 256-bit streaming load/store (sm_100+: LDG.E.256 / STG.E.256).
__device__ __forceinline__ void ldcs_v8(const float* __restrict__ p, float* r) {
    asm volatile("ld.global.cs.v8.f32 {%0,%1,%2,%3,%4,%5,%6,%7}, [%8];"
        : "=f"(r[0]), "=f"(r[1]), "=f"(r[2]), "=f"(r[3]),
          "=f"(r[4]), "=f"(r[5]), "=f"(r[6]), "=f"(r[7])
        : "l"(p));
}
__device__ __forceinline__ void stcs_v8(float* __restrict__ p, const float* r) {
    asm volatile("st.global.cs.v8.f32 [%0], {%1,%2,%3,%4,%5,%6,%7,%8};"
        :: "l"(p),
           "f"(r[0]), "f"(r[1]), "f"(r[2]), "f"(r[3]),
           "f"(r[4]), "f"(r[5]), "f"(r[6]), "f"(r[7])
        : "memory");
}

// out[u,i] = sum_v A[u][v] * x[v,i] + S[u] * noise[u,i]
//
// R9 geometry (16KB contiguous span/stream per block, batch-8 front loads,
// streaming cache ops) with vector width doubled to 256-bit: halves LSU
// request count at identical bytes/geometry.
__global__ __launch_bounds__(THREADS)
void fused_miso_kernel(const float* __restrict__ x,      // [U][NPER]
                       const float* __restrict__ noise,  // [U][NPER]
                       float* __restrict__ out,          // [U][NPER]
                       const float* __restrict__ W,      // [NT, U]
                       const float* __restrict__ H,      // [NT, U]
                       const float* __restrict__ P,      // [U]
                       const float* __restrict__ stddev) // [U]
{
    __shared__ float sG[NUM_U * NUM_U];
    __shared__ float sA[NUM_U * NUM_U];
    __shared__ float sS[NUM_U];

    const int t = threadIdx.x;

    // ---- per-block coefficient computation (16 threads, ~200 cycles) ----
    if (t < NUM_U * NUM_U) {
        const int u = t >> 2, v = t & 3;
        float acc = 0.f;
        #pragma unroll
        for (int n = 0; n < NUM_NT; n++)
            acc += H[n * NUM_U + u] * W[n * NUM_U + v];
        sG[t] = acc;
    }
    __syncthreads();
    if (t < NUM_U * NUM_U) {
        const int u = t >> 2, v = t & 3;
        const float inv_amp = 1.0f / (sqrtf(P[u]) * sG[u * NUM_U + u]);
        sA[t] = sqrtf(P[v]) * sG[t] * inv_amp;
        if (v == 0) sS[u] = stddev[u] * inv_amp;
    }
    __syncthreads();

    float a[NUM_U * NUM_U];
    #pragma unroll
    for (int k = 0; k < NUM_U * NUM_U; k++) a[k] = sA[k];
    float s[NUM_U];
    #pragma unroll
    for (int u = 0; u < NUM_U; u++) s[u] = sS[u];

    // ---- streaming main loop: block-contiguous tiling, 256-bit ops ----
    // Block b owns float8 positions [b*512, (b+1)*512) per stream,
    // covered in IPT8=2 steps of THREADS=256 (16KB contiguous per stream).
    const unsigned base = blockIdx.x * (THREADS * IPT8) + t;

    #pragma unroll
    for (int k = 0; k < IPT8; k++) {
        const unsigned i = base + (unsigned)k * THREADS;    // < N8 always

        // Front-batch ALL 8 (256-bit) loads before any math.
        float xv[NUM_U][8];
        float nv[NUM_U][8];
        #pragma unroll
        for (int v = 0; v < NUM_U; v++)
            ldcs_v8(x + ((size_t)v * N8 + i) * 8, xv[v]);
        #pragma unroll
        for (int u = 0; u < NUM_U; u++)
            ldcs_v8(noise + ((size_t)u * N8 + i) * 8, nv[u]);

        #pragma unroll
        for (int u = 0; u < NUM_U; u++) {
            const float a0 = a[u*NUM_U+0], a1 = a[u*NUM_U+1],
                        a2 = a[u*NUM_U+2], a3 = a[u*NUM_U+3];
            float o[8];
            #pragma unroll
            for (int j = 0; j < 8; j++)
                o[j] = fmaf(s[u], nv[u][j],
                        fmaf(a0, xv[0][j],
                         fmaf(a1, xv[1][j],
                          fmaf(a2, xv[2][j], a3 * xv[3][j]))));
            stcs_v8(out + ((size_t)u * N8 + i) * 8, o);
        }
    }
}

extern "C" void kernel_launch(void* const* d_in, const int* in_sizes, int n_in,
                              void* d_out, int out_size)
{
    // Input order per reference setup_inputs(): x, W, H, P, stddev, noise
    const float* x      = (const float*)d_in[0];
    const float* W      = (const float*)d_in[1];
    const float* H      = (const float*)d_in[2];
    const float* P      = (const float*)d_in[3];
    const float* stddev = (const float*)d_in[4];
    const float* noise  = (const float*)d_in[5];
    float* out = (float*)d_out;

    fused_miso_kernel<<<GRID, THREADS>>>(x, noise, out, W, H, P, stddev);
}